// round 11
// baseline (speedup 1.0000x reference)
#include <cuda_runtime.h>
#include <cuda_bf16.h>
#include <cstdint>

#define NMAX   60000
#define VMAX   50000
#define SEQL   30
#define HD     100
#define G3     300
#define NSM    152

typedef unsigned long long u64;

__device__ float g_embW[VMAX * G3];
__device__ float g_hn  [NMAX * HD];
__device__ float g_xw  [NMAX * HD];
__device__ float g_xc1 [NMAX * HD];
__device__ float g_xc2 [NMAX * HD];
__device__ float g_x   [NMAX * 2*HD];
__device__ float g_dinv[NMAX];
__device__ int   g_deg [NMAX];

__device__ __forceinline__ u64 pack2(float lo, float hi) {
    u64 r; asm("mov.b64 %0, {%1, %2};" : "=l"(r) : "f"(lo), "f"(hi)); return r;
}
__device__ __forceinline__ void unpack2(u64 v, float &lo, float &hi) {
    asm("mov.b64 {%0, %1}, %2;" : "=f"(lo), "=f"(hi) : "l"(v));
}
__device__ __forceinline__ u64 fma2(u64 a, u64 b, u64 c) {
    u64 d; asm("fma.rn.f32x2 %0, %1, %2, %3;" : "=l"(d) : "l"(a), "l"(b), "l"(c)); return d;
}
__device__ __forceinline__ float sigmf(float x) { return __fdividef(1.f, 1.f + __expf(-x)); }
__device__ __forceinline__ float tanh_f(float x) {
    return fmaf(2.f, __fdividef(1.f, 1.f + __expf(-2.f * x)), -1.f);
}
__device__ __forceinline__ float bf16f(uint32_t b16) {
    uint32_t u = b16 << 16; float f; asm("mov.b32 %0, %1;" : "=f"(f) : "r"(u)); return f;
}
__device__ __forceinline__ uint32_t s2u(const void* p) {
    uint32_t a; asm("{ .reg .u64 t; cvta.to.shared.u64 t, %1; cvt.u32.u64 %0, t; }" : "=r"(a) : "l"(p));
    return a;
}

// ================= degree =================
__global__ void k_deg_init(int N) {
    int i = blockIdx.x * blockDim.x + threadIdx.x; if (i < N) g_deg[i] = 1;
}
__global__ void k_deg_edges(const int* __restrict__ ei, int E) {
    int e = blockIdx.x * blockDim.x + threadIdx.x; if (e < E) atomicAdd(&g_deg[ei[E + e]], 1);
}
__global__ void k_dinv(int N) {
    int i = blockIdx.x * blockDim.x + threadIdx.x; if (i < N) g_dinv[i] = rsqrtf((float)g_deg[i]);
}

// ================= embW table (fp32, proven) =================
#define EMBW_SMEM ((30000 + 6400) * 4)
__global__ __launch_bounds__(320, 1)
void k_embW(const float* __restrict__ emb, const float* __restrict__ W_ih,
            const float* __restrict__ b_ih, int V, int ntiles)
{
    extern __shared__ float sm[];
    float* sW = sm; float* se = sm + 30000;
    const int tid = threadIdx.x, n = tid & 63, jc = tid >> 6;
    for (int idx = tid; idx < G3 * HD; idx += 320) {
        int c = idx / HD, k = idx - c * HD;
        sW[k * G3 + c] = W_ih[idx];
    }
    for (int tile = blockIdx.x; tile < ntiles; tile += gridDim.x) {
        const int base = tile * 64;
        __syncthreads();
        for (int idx = tid; idx < 64 * HD; idx += 320) {
            int nn = idx / HD, k = idx - nn * HD;
            se[k * 64 + nn] = emb[min(base + nn, V - 1) * HD + k];
        }
        __syncthreads();
        u64 acc[30];
        #pragma unroll
        for (int p = 0; p < 30; p++) acc[p] = 0ull;
        const float* wr0 = sW + jc * 60;
        #pragma unroll 2
        for (int k = 0; k < HD; k++) {
            float xv = se[k * 64 + n];
            u64 x2 = pack2(xv, xv);
            const float* wr = wr0 + k * G3;
            #pragma unroll
            for (int p = 0; p < 30; p++) acc[p] = fma2(*(const u64*)(wr + p * 2), x2, acc[p]);
        }
        int v = base + n;
        if (v < V) {
            float* o = g_embW + (long long)v * G3 + jc * 60;
            const float* bp = b_ih + jc * 60;
            #pragma unroll
            for (int p = 0; p < 30; p++) {
                float lo, hi; unpack2(acc[p], lo, hi);
                float2 w; w.x = lo + bp[p*2]; w.y = hi + bp[p*2+1];
                *(float2*)(o + p*2) = w;
            }
        }
    }
}

// ================= HMMA GRU (mma.sync m16n8k16 bf16, 384 thr) =================
// 96-node tile = 6 m-tiles. 12 warps = 3 m-groups (2 m-tiles each) x 4
// n-quarters (q split 4/3/3/3 over 13 q-cols per gate). Each B fragment is
// loaded ONCE and used for TWO mmas (both m-tiles) -> B LDS traffic halves.
#define FRAG_OFF 0
#define A_OFF    139776
#define A_STR    496
#define NT       96
#define TOK_OFF  187392
#define BHH_OFF  198912
#define MMASMEM  200192

__global__ __launch_bounds__(384, 1)
void k_gru_mma(const float* __restrict__ h0, const int* __restrict__ feat,
               const float* __restrict__ W_hh, const float* __restrict__ b_hh,
               int n_nodes, int ntiles)
{
    extern __shared__ char smc[];
    const uint32_t sb = s2u(smc);
    const int tid = threadIdx.x, wid = tid >> 5, lane = tid & 31;
    const int nq = wid & 3, mg = wid >> 2;          // mg 0..2, nq 0..3
    const int g = lane >> 2, t = lane & 3;
    const int qlo  = (nq == 0) ? 0 : 1 + 3 * nq;    // 0,4,7,10
    const int qcnt = (nq == 0) ? 4 : 3;
    float* sbhh = (float*)(smc + BHH_OFF);
    int*   stok = (int*)(smc + TOK_OFF);

    // ---- one-time: B fragments + biases ----
    for (int w = tid; w < 14 * 39 * 32; w += 384) {
        int lan = w & 31, tile = w >> 5;
        int nt = tile % 39, ktd = tile / 39;
        int gg = lan >> 2, tt = lan & 3;
        int gate = nt / 13, j = (nt % 13) * 8 + gg;
        bool isLo = (ktd >= 7);
        int k0 = (isLo ? ktd - 7 : ktd) * 16 + tt * 2;
        uint32_t br[2];
        #pragma unroll
        for (int r = 0; r < 2; r++) {
            uint32_t pk = 0;
            #pragma unroll
            for (int e = 0; e < 2; e++) {
                int kk = k0 + r * 8 + e;
                uint16_t bits = 0;
                if (j < 100 && kk < 100) {
                    float wv = W_hh[(gate * 100 + j) * 100 + kk];
                    __nv_bfloat16 hb = __float2bfloat16_rn(wv);
                    if (isLo) hb = __float2bfloat16_rn(wv - __bfloat162float(hb));
                    bits = __bfloat16_as_ushort(hb);
                }
                pk |= (uint32_t)bits << (16 * e);
            }
            br[r] = pk;
        }
        *(uint2*)(smc + FRAG_OFF + tile * 256 + lan * 8) = make_uint2(br[0], br[1]);
    }
    for (int i = tid; i < G3; i += 384) sbhh[i] = b_hh[i];
    __syncthreads();

    const int m0row = mg * 32;     // this warp's 32 rows (2 m-tiles)

    for (int tile = blockIdx.x; tile < ntiles; tile += gridDim.x) {
        const int nbase = tile * NT;
        __syncthreads();
        for (int i = tid; i < NT * SEQL; i += 384) {
            int nl = i / SEQL, tt = i - nl * SEQL;
            stok[nl * SEQL + tt] = feat[(long long)min(nbase + nl, n_nodes - 1) * SEQL + tt];
        }
        for (int i = tid; i < NT * 248; i += 384) {
            int row = i / 248, col = i - row * 248;
            uint16_t v = 0;
            if (col < 224) {
                int seg = col / 112, k = col - seg * 112;
                if (k < 100) {
                    float hv = h0[(long long)min(nbase + row, n_nodes - 1) * HD + k];
                    __nv_bfloat16 hb = __float2bfloat16_rn(hv);
                    if (seg == 1) hb = __float2bfloat16_rn(hv - __bfloat162float(hb));
                    v = __bfloat16_as_ushort(hb);
                }
            }
            *(uint16_t*)(smc + A_OFF + row * A_STR + col * 2) = v;
        }
        __syncthreads();

        for (int st = 0; st < SEQL; st++) {
            // ---- GEMM: gh = [h_hi|h_lo|h_hi] x [W_hi|W_hi|W_lo] ----
            float C0[3][4][4], C1[3][4][4];
            #pragma unroll
            for (int ga = 0; ga < 3; ga++)
                #pragma unroll
                for (int qi = 0; qi < 4; qi++)
                    #pragma unroll
                    for (int e = 0; e < 4; e++) { C0[ga][qi][e] = 0.f; C1[ga][qi][e] = 0.f; }

            const uint32_t ab0 = sb + A_OFF + (m0row + (lane & 15)) * A_STR + (lane >> 4) * 16;
            const uint32_t ab1 = ab0 + 16 * A_STR;
            #pragma unroll
            for (int kt = 0; kt < 21; kt++) {
                int acol = (kt < 7) ? kt * 32 : (kt < 14) ? 224 + (kt - 7) * 32 : (kt - 14) * 32;
                int ktd  = (kt < 7) ? kt : kt - 7;
                uint32_t a0, a1, a2, a3, c0, c1, c2, c3;
                asm volatile("ldmatrix.sync.aligned.m8n8.x4.shared.b16 {%0,%1,%2,%3}, [%4];"
                    : "=r"(a0), "=r"(a1), "=r"(a2), "=r"(a3) : "r"(ab0 + acol));
                asm volatile("ldmatrix.sync.aligned.m8n8.x4.shared.b16 {%0,%1,%2,%3}, [%4];"
                    : "=r"(c0), "=r"(c1), "=r"(c2), "=r"(c3) : "r"(ab1 + acol));
                #pragma unroll
                for (int ga = 0; ga < 3; ga++) {
                    #pragma unroll
                    for (int qi = 0; qi < 4; qi++) {
                        if (qi < qcnt) {
                            int nt = ga * 13 + qlo + qi;
                            uint32_t b0, b1;
                            asm volatile("ld.shared.v2.b32 {%0,%1}, [%2];"
                                : "=r"(b0), "=r"(b1)
                                : "r"(sb + FRAG_OFF + (ktd * 39 + nt) * 256 + lane * 8));
                            asm volatile(
                                "mma.sync.aligned.m16n8k16.row.col.f32.bf16.bf16.f32 "
                                "{%0,%1,%2,%3}, {%4,%5,%6,%7}, {%8,%9}, {%0,%1,%2,%3};"
                                : "+f"(C0[ga][qi][0]), "+f"(C0[ga][qi][1]),
                                  "+f"(C0[ga][qi][2]), "+f"(C0[ga][qi][3])
                                : "r"(a0), "r"(a1), "r"(a2), "r"(a3), "r"(b0), "r"(b1));
                            asm volatile(
                                "mma.sync.aligned.m16n8k16.row.col.f32.bf16.bf16.f32 "
                                "{%0,%1,%2,%3}, {%4,%5,%6,%7}, {%8,%9}, {%0,%1,%2,%3};"
                                : "+f"(C1[ga][qi][0]), "+f"(C1[ga][qi][1]),
                                  "+f"(C1[ga][qi][2]), "+f"(C1[ga][qi][3])
                                : "r"(c0), "r"(c1), "r"(c2), "r"(c3), "r"(b0), "r"(b1));
                        }
                    }
                }
            }
            __syncthreads();   // all A reads done before h writes

            // ---- gate phase ----
            const bool last = (st == SEQL - 1);
            #pragma unroll
            for (int qi = 0; qi < 4; qi++) {
                if (qi < qcnt) {
                    int j = (qlo + qi) * 8 + 2 * t;
                    if (j < 100) {
                        float2 bhr = *(const float2*)(sbhh + j);
                        float2 bhz = *(const float2*)(sbhh + 100 + j);
                        float2 bhn = *(const float2*)(sbhh + 200 + j);
                        #pragma unroll
                        for (int mt = 0; mt < 2; mt++) {
                            #pragma unroll
                            for (int nd = 0; nd < 2; nd++) {
                                int nl = m0row + mt * 16 + nd * 8 + g;
                                int gn = nbase + nl;
                                int tok = stok[nl * SEQL + st];
                                const float* ew = g_embW + (long long)tok * G3;
                                float2 xr = __ldg((const float2*)(ew + j));
                                float2 xz = __ldg((const float2*)(ew + 100 + j));
                                float2 xn = __ldg((const float2*)(ew + 200 + j));
                                char* hrow = smc + A_OFF + nl * A_STR;
                                uint32_t hhi = *(uint32_t*)(hrow + 2 * j);
                                uint32_t hlo = *(uint32_t*)(hrow + 224 + 2 * j);
                                float ho0 = bf16f(hhi & 0xffffu) + bf16f(hlo & 0xffffu);
                                float ho1 = bf16f(hhi >> 16) + bf16f(hlo >> 16);
                                float cr0 = mt ? C1[0][qi][2*nd]   : C0[0][qi][2*nd];
                                float cr1 = mt ? C1[0][qi][2*nd+1] : C0[0][qi][2*nd+1];
                                float cz0 = mt ? C1[1][qi][2*nd]   : C0[1][qi][2*nd];
                                float cz1 = mt ? C1[1][qi][2*nd+1] : C0[1][qi][2*nd+1];
                                float cn0 = mt ? C1[2][qi][2*nd]   : C0[2][qi][2*nd];
                                float cn1 = mt ? C1[2][qi][2*nd+1] : C0[2][qi][2*nd+1];
                                float r0 = sigmf(xr.x + cr0 + bhr.x);
                                float r1 = sigmf(xr.y + cr1 + bhr.y);
                                float z0 = sigmf(xz.x + cz0 + bhz.x);
                                float z1 = sigmf(xz.y + cz1 + bhz.y);
                                float nv0 = tanh_f(xn.x + r0 * (cn0 + bhn.x));
                                float nv1 = tanh_f(xn.y + r1 * (cn1 + bhn.y));
                                float h0n = nv0 + z0 * (ho0 - nv0);
                                float h1n = nv1 + z1 * (ho1 - nv1);
                                if (last) {
                                    if (gn < n_nodes)
                                        *(float2*)(g_hn + (long long)gn * HD + j) = make_float2(h0n, h1n);
                                } else {
                                    __nv_bfloat16 ah = __float2bfloat16_rn(h0n);
                                    __nv_bfloat16 bh = __float2bfloat16_rn(h1n);
                                    __nv_bfloat16 al = __float2bfloat16_rn(h0n - __bfloat162float(ah));
                                    __nv_bfloat16 bl = __float2bfloat16_rn(h1n - __bfloat162float(bh));
                                    *(uint32_t*)(hrow + 2 * j) =
                                        (uint32_t)__bfloat16_as_ushort(ah) |
                                        ((uint32_t)__bfloat16_as_ushort(bh) << 16);
                                    *(uint32_t*)(hrow + 224 + 2 * j) =
                                        (uint32_t)__bfloat16_as_ushort(al) |
                                        ((uint32_t)__bfloat16_as_ushort(bl) << 16);
                                }
                            }
                        }
                    }
                }
            }
            __syncthreads();   // h writes visible before next step's GEMM
        }
    }
}

// ================= small GEMMs / GCN / glue (proven) =================
template<int K>
__device__ __forceinline__ void gemm_body(const float* __restrict__ x,
    const float* __restrict__ W, float* __restrict__ outp, int N)
{
    extern __shared__ float sg[];
    float* sxT = sg; float* sW = sg + K * 64;
    const int tid = threadIdx.x, base = blockIdx.x * 64;
    for (int idx = tid; idx < K * 64; idx += 256) {
        int nn = idx / K, k = idx - nn * K;
        sxT[k * 64 + nn] = x[min(base + nn, N - 1) * K + k];
    }
    for (int idx = tid; idx < K * 100; idx += 256) sW[idx] = W[idx];
    __syncthreads();
    const int n = tid & 63, q = tid >> 6;
    float acc[25];
    #pragma unroll
    for (int j = 0; j < 25; j++) acc[j] = 0.f;
    #pragma unroll 4
    for (int k = 0; k < K; k++) {
        float xk = sxT[k * 64 + n];
        const float* wr = sW + k * 100 + q * 25;
        #pragma unroll
        for (int j = 0; j < 25; j++) acc[j] = fmaf(xk, wr[j], acc[j]);
    }
    int ng = base + n;
    if (ng < N) {
        float* o = outp + ng * 100 + q * 25;
        #pragma unroll
        for (int j = 0; j < 25; j++) o[j] = acc[j];
    }
}
__global__ __launch_bounds__(256) void k_gemm1(const float* __restrict__ W1, int N) {
    gemm_body<100>(g_hn, W1, g_xw, N);
}
__global__ __launch_bounds__(256) void k_gemm2(const float* __restrict__ W2, int N) {
    gemm_body<200>(g_x, W2, g_xw, N);
}
__device__ __forceinline__ void init_self(const float* __restrict__ b, float* __restrict__ o, int N) {
    int gid = blockIdx.x * blockDim.x + threadIdx.x;
    if (gid >= N * HD) return;
    int n = gid / HD, j = gid - n * HD;
    float di = g_dinv[n];
    o[gid] = fmaf(g_xw[gid], di * di, b[j]);
}
__global__ void k_init1(const float* __restrict__ b1, int N) { init_self(b1, g_xc1, N); }
__global__ void k_init2(const float* __restrict__ b2, int N) { init_self(b2, g_xc2, N); }
__device__ __forceinline__ void edge_body(float* __restrict__ o, const int* __restrict__ ei, int E) {
    int gid = blockIdx.x * blockDim.x + threadIdx.x;
    if (gid >= E * 25) return;
    int e = gid / 25, c = gid - e * 25;
    int src = ei[e], dst = ei[E + e];
    float coef = g_dinv[src] * g_dinv[dst];
    float4 v = *(const float4*)(g_xw + src * HD + c * 4);
    float* op = o + dst * HD + c * 4;
    atomicAdd(op + 0, v.x * coef); atomicAdd(op + 1, v.y * coef);
    atomicAdd(op + 2, v.z * coef); atomicAdd(op + 3, v.w * coef);
}
__global__ void k_edge1(const int* __restrict__ ei, int E) { edge_body(g_xc1, ei, E); }
__global__ void k_edge2(const int* __restrict__ ei, int E) { edge_body(g_xc2, ei, E); }
__global__ void k_build_x(const int* __restrict__ idc, int N) {
    int gid = blockIdx.x * blockDim.x + threadIdx.x;
    if (gid >= N * 2 * HD) return;
    int n = gid / (2 * HD), j = gid - n * 2 * HD;
    float v = (j < HD) ? g_xc1[n * HD + j] : g_hn[idc[n] * HD + (j - HD)];
    g_x[gid] = fmaxf(v, 0.f);
}
__global__ void k_final(const int* __restrict__ idc, float* __restrict__ out, int N) {
    int gid = blockIdx.x * blockDim.x + threadIdx.x;
    if (gid >= N * 2 * HD) return;
    int n = gid / (2 * HD), j = gid - n * 2 * HD;
    out[gid] = (j < HD) ? fmaxf(g_xc2[n * HD + j], 0.f) : g_xc1[idc[n] * HD + (j - HD)];
}

extern "C" void kernel_launch(void* const* d_in, const int* in_sizes, int n_in,
                              void* d_out, int out_size)
{
    const int*   feat    = (const int*)  d_in[0];
    const int*   ei      = (const int*)  d_in[1];
    const int*   indices = (const int*)  d_in[2];
    const float* h0      = (const float*)d_in[3];
    const float* emb     = (const float*)d_in[4];
    const float* W_ih    = (const float*)d_in[5];
    const float* W_hh    = (const float*)d_in[6];
    const float* b_ih    = (const float*)d_in[7];
    const float* b_hh    = (const float*)d_in[8];
    const float* W1      = (const float*)d_in[9];
    const float* b1      = (const float*)d_in[10];
    const float* W2      = (const float*)d_in[11];
    const float* b2      = (const float*)d_in[12];
    float* out = (float*)d_out;

    const int N = in_sizes[0] / SEQL;
    const int E = in_sizes[1] / 2;
    const int V = in_sizes[4] / HD;
    const int gtiles = (N + NT - 1) / NT;
    const int etiles = (V + 63) / 64;

    cudaFuncSetAttribute(k_gru_mma, cudaFuncAttributeMaxDynamicSharedMemorySize, MMASMEM);
    cudaFuncSetAttribute(k_embW,    cudaFuncAttributeMaxDynamicSharedMemorySize, EMBW_SMEM);
    cudaFuncSetAttribute(k_gemm1,   cudaFuncAttributeMaxDynamicSharedMemorySize, (100*64 + 100*100) * 4);
    cudaFuncSetAttribute(k_gemm2,   cudaFuncAttributeMaxDynamicSharedMemorySize, (200*64 + 200*100) * 4);

    k_deg_init <<<(N + 255) / 256, 256>>>(N);
    k_deg_edges<<<(E + 255) / 256, 256>>>(ei, E);
    k_embW<<<NSM, 320, EMBW_SMEM>>>(emb, W_ih, b_ih, V, etiles);
    k_gru_mma<<<NSM, 384, MMASMEM>>>(h0, feat, W_hh, b_hh, N, gtiles);   // ncu slot 3
    k_dinv<<<(N + 255) / 256, 256>>>(N);

    k_gemm1<<<(N + 63) / 64, 256, (100*64 + 100*100) * 4>>>(W1, N);
    k_init1<<<(N * HD + 255) / 256, 256>>>(b1, N);
    k_edge1<<<(E * 25 + 255) / 256, 256>>>(ei, E);
    k_build_x<<<(N * 2 * HD + 255) / 256, 256>>>(indices, N);
    k_gemm2<<<(N + 63) / 64, 256, (200*64 + 200*100) * 4>>>(W2, N);
    k_init2<<<(N * HD + 255) / 256, 256>>>(b2, N);
    k_edge2<<<(E * 25 + 255) / 256, 256>>>(ei, E);
    k_final<<<(N * 2 * HD + 255) / 256, 256>>>(indices, out, N);
}

// round 12
// speedup vs baseline: 1.0876x; 1.0876x over previous
#include <cuda_runtime.h>
#include <cuda_bf16.h>
#include <cstdint>

#define NMAX   60000
#define VMAX   50000
#define SEQL   30
#define HD     100
#define G3     300
#define NSM    152

typedef unsigned long long u64;

__device__ float g_embW[VMAX * G3];
__device__ float g_hn  [NMAX * HD];
__device__ float g_xw  [NMAX * HD];
__device__ float g_xc1 [NMAX * HD];
__device__ float g_xc2 [NMAX * HD];
__device__ float g_x   [NMAX * 2*HD];
__device__ float g_dinv[NMAX];
__device__ int   g_deg [NMAX];

__device__ __forceinline__ u64 pack2(float lo, float hi) {
    u64 r; asm("mov.b64 %0, {%1, %2};" : "=l"(r) : "f"(lo), "f"(hi)); return r;
}
__device__ __forceinline__ void unpack2(u64 v, float &lo, float &hi) {
    asm("mov.b64 {%0, %1}, %2;" : "=f"(lo), "=f"(hi) : "l"(v));
}
__device__ __forceinline__ u64 fma2(u64 a, u64 b, u64 c) {
    u64 d; asm("fma.rn.f32x2 %0, %1, %2, %3;" : "=l"(d) : "l"(a), "l"(b), "l"(c)); return d;
}
__device__ __forceinline__ float sigmf(float x) { return __fdividef(1.f, 1.f + __expf(-x)); }
__device__ __forceinline__ float tanh_f(float x) {
    return fmaf(2.f, __fdividef(1.f, 1.f + __expf(-2.f * x)), -1.f);
}
__device__ __forceinline__ float bf16f(uint32_t b16) {
    uint32_t u = b16 << 16; float f; asm("mov.b32 %0, %1;" : "=f"(f) : "r"(u)); return f;
}
__device__ __forceinline__ uint32_t s2u(const void* p) {
    uint32_t a; asm("{ .reg .u64 t; cvta.to.shared.u64 t, %1; cvt.u32.u64 %0, t; }" : "=r"(a) : "l"(p));
    return a;
}

// ================= degree =================
__global__ void k_deg_init(int N) {
    int i = blockIdx.x * blockDim.x + threadIdx.x; if (i < N) g_deg[i] = 1;
}
__global__ void k_deg_edges(const int* __restrict__ ei, int E) {
    int e = blockIdx.x * blockDim.x + threadIdx.x; if (e < E) atomicAdd(&g_deg[ei[E + e]], 1);
}
__global__ void k_dinv(int N) {
    int i = blockIdx.x * blockDim.x + threadIdx.x; if (i < N) g_dinv[i] = rsqrtf((float)g_deg[i]);
}

// ================= embW table (fp32, proven) =================
#define EMBW_SMEM ((30000 + 6400) * 4)
__global__ __launch_bounds__(320, 1)
void k_embW(const float* __restrict__ emb, const float* __restrict__ W_ih,
            const float* __restrict__ b_ih, int V, int ntiles)
{
    extern __shared__ float sm[];
    float* sW = sm; float* se = sm + 30000;
    const int tid = threadIdx.x, n = tid & 63, jc = tid >> 6;
    for (int idx = tid; idx < G3 * HD; idx += 320) {
        int c = idx / HD, k = idx - c * HD;
        sW[k * G3 + c] = W_ih[idx];
    }
    for (int tile = blockIdx.x; tile < ntiles; tile += gridDim.x) {
        const int base = tile * 64;
        __syncthreads();
        for (int idx = tid; idx < 64 * HD; idx += 320) {
            int nn = idx / HD, k = idx - nn * HD;
            se[k * 64 + nn] = emb[min(base + nn, V - 1) * HD + k];
        }
        __syncthreads();
        u64 acc[30];
        #pragma unroll
        for (int p = 0; p < 30; p++) acc[p] = 0ull;
        const float* wr0 = sW + jc * 60;
        #pragma unroll 2
        for (int k = 0; k < HD; k++) {
            float xv = se[k * 64 + n];
            u64 x2 = pack2(xv, xv);
            const float* wr = wr0 + k * G3;
            #pragma unroll
            for (int p = 0; p < 30; p++) acc[p] = fma2(*(const u64*)(wr + p * 2), x2, acc[p]);
        }
        int v = base + n;
        if (v < V) {
            float* o = g_embW + (long long)v * G3 + jc * 60;
            const float* bp = b_ih + jc * 60;
            #pragma unroll
            for (int p = 0; p < 30; p++) {
                float lo, hi; unpack2(acc[p], lo, hi);
                float2 w; w.x = lo + bp[p*2]; w.y = hi + bp[p*2+1];
                *(float2*)(o + p*2) = w;
            }
        }
    }
}

// ================= HMMA GRU (mma.sync m16n8k16 bf16, 640 thr) =================
// 80-node tile = 5 m-tiles. 20 warps = 5 m-tiles x 4 n-quarters
// (q split 4/3/3/3 over 13 q-cols per gate). C = 48 regs/warp, 5 warps/SMSP.
#define FRAG_OFF 0
#define A_OFF    139776
#define A_STR    496
#define NT       80
#define TOK_OFF  179456
#define BHH_OFF  189056
#define MMASMEM  190464

__global__ __launch_bounds__(640, 1)
void k_gru_mma(const float* __restrict__ h0, const int* __restrict__ feat,
               const float* __restrict__ W_hh, const float* __restrict__ b_hh,
               int n_nodes, int ntiles)
{
    extern __shared__ char smc[];
    const uint32_t sb = s2u(smc);
    const int tid = threadIdx.x, wid = tid >> 5, lane = tid & 31;
    const int nq = wid & 3, m = wid >> 2;           // m 0..4, nq 0..3
    const int g = lane >> 2, t = lane & 3;
    const int qlo  = (nq == 0) ? 0 : 1 + 3 * nq;    // 0,4,7,10
    const int qcnt = (nq == 0) ? 4 : 3;
    float* sbhh = (float*)(smc + BHH_OFF);
    int*   stok = (int*)(smc + TOK_OFF);

    // ---- one-time: B fragments + biases ----
    for (int w = tid; w < 14 * 39 * 32; w += 640) {
        int lan = w & 31, tile = w >> 5;
        int nt = tile % 39, ktd = tile / 39;
        int gg = lan >> 2, tt = lan & 3;
        int gate = nt / 13, j = (nt % 13) * 8 + gg;
        bool isLo = (ktd >= 7);
        int k0 = (isLo ? ktd - 7 : ktd) * 16 + tt * 2;
        uint32_t br[2];
        #pragma unroll
        for (int r = 0; r < 2; r++) {
            uint32_t pk = 0;
            #pragma unroll
            for (int e = 0; e < 2; e++) {
                int kk = k0 + r * 8 + e;
                uint16_t bits = 0;
                if (j < 100 && kk < 100) {
                    float wv = W_hh[(gate * 100 + j) * 100 + kk];
                    __nv_bfloat16 hb = __float2bfloat16_rn(wv);
                    if (isLo) hb = __float2bfloat16_rn(wv - __bfloat162float(hb));
                    bits = __bfloat16_as_ushort(hb);
                }
                pk |= (uint32_t)bits << (16 * e);
            }
            br[r] = pk;
        }
        *(uint2*)(smc + FRAG_OFF + tile * 256 + lan * 8) = make_uint2(br[0], br[1]);
    }
    for (int i = tid; i < G3; i += 640) sbhh[i] = b_hh[i];
    __syncthreads();

    const int n0l = m * 16 + g, n1l = n0l + 8;

    for (int tile = blockIdx.x; tile < ntiles; tile += gridDim.x) {
        const int nbase = tile * NT;
        __syncthreads();
        for (int i = tid; i < NT * SEQL; i += 640) {
            int nl = i / SEQL, tt = i - nl * SEQL;
            stok[nl * SEQL + tt] = feat[(long long)min(nbase + nl, n_nodes - 1) * SEQL + tt];
        }
        for (int i = tid; i < NT * 248; i += 640) {
            int row = i / 248, col = i - row * 248;
            uint16_t v = 0;
            if (col < 224) {
                int seg = col / 112, k = col - seg * 112;
                if (k < 100) {
                    float hv = h0[(long long)min(nbase + row, n_nodes - 1) * HD + k];
                    __nv_bfloat16 hb = __float2bfloat16_rn(hv);
                    if (seg == 1) hb = __float2bfloat16_rn(hv - __bfloat162float(hb));
                    v = __bfloat16_as_ushort(hb);
                }
            }
            *(uint16_t*)(smc + A_OFF + row * A_STR + col * 2) = v;
        }
        __syncthreads();

        for (int st = 0; st < SEQL; st++) {
            // ---- GEMM: gh = [h_hi|h_lo|h_hi] x [W_hi|W_hi|W_lo] ----
            float C[3][4][4];
            #pragma unroll
            for (int ga = 0; ga < 3; ga++)
                #pragma unroll
                for (int qi = 0; qi < 4; qi++)
                    #pragma unroll
                    for (int e = 0; e < 4; e++) C[ga][qi][e] = 0.f;

            const uint32_t abase = sb + A_OFF + (m * 16 + (lane & 15)) * A_STR + (lane >> 4) * 16;
            #pragma unroll
            for (int kt = 0; kt < 21; kt++) {
                int acol = (kt < 7) ? kt * 32 : (kt < 14) ? 224 + (kt - 7) * 32 : (kt - 14) * 32;
                int ktd  = (kt < 7) ? kt : kt - 7;
                uint32_t a0, a1, a2, a3;
                asm volatile("ldmatrix.sync.aligned.m8n8.x4.shared.b16 {%0,%1,%2,%3}, [%4];"
                    : "=r"(a0), "=r"(a1), "=r"(a2), "=r"(a3) : "r"(abase + acol));
                #pragma unroll
                for (int ga = 0; ga < 3; ga++) {
                    #pragma unroll
                    for (int qi = 0; qi < 4; qi++) {
                        if (qi < qcnt) {
                            int nt = ga * 13 + qlo + qi;
                            uint32_t b0, b1;
                            asm volatile("ld.shared.v2.b32 {%0,%1}, [%2];"
                                : "=r"(b0), "=r"(b1)
                                : "r"(sb + FRAG_OFF + (ktd * 39 + nt) * 256 + lane * 8));
                            asm volatile(
                                "mma.sync.aligned.m16n8k16.row.col.f32.bf16.bf16.f32 "
                                "{%0,%1,%2,%3}, {%4,%5,%6,%7}, {%8,%9}, {%0,%1,%2,%3};"
                                : "+f"(C[ga][qi][0]), "+f"(C[ga][qi][1]),
                                  "+f"(C[ga][qi][2]), "+f"(C[ga][qi][3])
                                : "r"(a0), "r"(a1), "r"(a2), "r"(a3), "r"(b0), "r"(b1));
                        }
                    }
                }
            }
            __syncthreads();   // all A reads done before h writes

            // ---- gate phase ----
            const bool last = (st == SEQL - 1);
            #pragma unroll
            for (int qi = 0; qi < 4; qi++) {
                if (qi < qcnt) {
                    int j = (qlo + qi) * 8 + 2 * t;
                    if (j < 100) {
                        float2 bhr = *(const float2*)(sbhh + j);
                        float2 bhz = *(const float2*)(sbhh + 100 + j);
                        float2 bhn = *(const float2*)(sbhh + 200 + j);
                        #pragma unroll
                        for (int nd = 0; nd < 2; nd++) {
                            int nl = nd ? n1l : n0l;
                            int gn = nbase + nl;
                            int tok = stok[nl * SEQL + st];
                            const float* ew = g_embW + (long long)tok * G3;
                            float2 xr = __ldg((const float2*)(ew + j));
                            float2 xz = __ldg((const float2*)(ew + 100 + j));
                            float2 xn = __ldg((const float2*)(ew + 200 + j));
                            char* hrow = smc + A_OFF + nl * A_STR;
                            uint32_t hhi = *(uint32_t*)(hrow + 2 * j);
                            uint32_t hlo = *(uint32_t*)(hrow + 224 + 2 * j);
                            float ho0 = bf16f(hhi & 0xffffu) + bf16f(hlo & 0xffffu);
                            float ho1 = bf16f(hhi >> 16) + bf16f(hlo >> 16);
                            float r0 = sigmf(xr.x + C[0][qi][2*nd]   + bhr.x);
                            float r1 = sigmf(xr.y + C[0][qi][2*nd+1] + bhr.y);
                            float z0 = sigmf(xz.x + C[1][qi][2*nd]   + bhz.x);
                            float z1 = sigmf(xz.y + C[1][qi][2*nd+1] + bhz.y);
                            float nv0 = tanh_f(xn.x + r0 * (C[2][qi][2*nd]   + bhn.x));
                            float nv1 = tanh_f(xn.y + r1 * (C[2][qi][2*nd+1] + bhn.y));
                            float h0n = nv0 + z0 * (ho0 - nv0);
                            float h1n = nv1 + z1 * (ho1 - nv1);
                            if (last) {
                                if (gn < n_nodes)
                                    *(float2*)(g_hn + (long long)gn * HD + j) = make_float2(h0n, h1n);
                            } else {
                                __nv_bfloat16 ah = __float2bfloat16_rn(h0n);
                                __nv_bfloat16 bh = __float2bfloat16_rn(h1n);
                                __nv_bfloat16 al = __float2bfloat16_rn(h0n - __bfloat162float(ah));
                                __nv_bfloat16 bl = __float2bfloat16_rn(h1n - __bfloat162float(bh));
                                *(uint32_t*)(hrow + 2 * j) =
                                    (uint32_t)__bfloat16_as_ushort(ah) |
                                    ((uint32_t)__bfloat16_as_ushort(bh) << 16);
                                *(uint32_t*)(hrow + 224 + 2 * j) =
                                    (uint32_t)__bfloat16_as_ushort(al) |
                                    ((uint32_t)__bfloat16_as_ushort(bl) << 16);
                            }
                        }
                    }
                }
            }
            __syncthreads();   // h writes visible before next step's GEMM
        }
    }
}

// ================= small GEMMs / GCN / glue (proven) =================
template<int K>
__device__ __forceinline__ void gemm_body(const float* __restrict__ x,
    const float* __restrict__ W, float* __restrict__ outp, int N)
{
    extern __shared__ float sg[];
    float* sxT = sg; float* sW = sg + K * 64;
    const int tid = threadIdx.x, base = blockIdx.x * 64;
    for (int idx = tid; idx < K * 64; idx += 256) {
        int nn = idx / K, k = idx - nn * K;
        sxT[k * 64 + nn] = x[min(base + nn, N - 1) * K + k];
    }
    for (int idx = tid; idx < K * 100; idx += 256) sW[idx] = W[idx];
    __syncthreads();
    const int n = tid & 63, q = tid >> 6;
    float acc[25];
    #pragma unroll
    for (int j = 0; j < 25; j++) acc[j] = 0.f;
    #pragma unroll 4
    for (int k = 0; k < K; k++) {
        float xk = sxT[k * 64 + n];
        const float* wr = sW + k * 100 + q * 25;
        #pragma unroll
        for (int j = 0; j < 25; j++) acc[j] = fmaf(xk, wr[j], acc[j]);
    }
    int ng = base + n;
    if (ng < N) {
        float* o = outp + ng * 100 + q * 25;
        #pragma unroll
        for (int j = 0; j < 25; j++) o[j] = acc[j];
    }
}
__global__ __launch_bounds__(256) void k_gemm1(const float* __restrict__ W1, int N) {
    gemm_body<100>(g_hn, W1, g_xw, N);
}
__global__ __launch_bounds__(256) void k_gemm2(const float* __restrict__ W2, int N) {
    gemm_body<200>(g_x, W2, g_xw, N);
}
__device__ __forceinline__ void init_self(const float* __restrict__ b, float* __restrict__ o, int N) {
    int gid = blockIdx.x * blockDim.x + threadIdx.x;
    if (gid >= N * HD) return;
    int n = gid / HD, j = gid - n * HD;
    float di = g_dinv[n];
    o[gid] = fmaf(g_xw[gid], di * di, b[j]);
}
__global__ void k_init1(const float* __restrict__ b1, int N) { init_self(b1, g_xc1, N); }
__global__ void k_init2(const float* __restrict__ b2, int N) { init_self(b2, g_xc2, N); }
__device__ __forceinline__ void edge_body(float* __restrict__ o, const int* __restrict__ ei, int E) {
    int gid = blockIdx.x * blockDim.x + threadIdx.x;
    if (gid >= E * 25) return;
    int e = gid / 25, c = gid - e * 25;
    int src = ei[e], dst = ei[E + e];
    float coef = g_dinv[src] * g_dinv[dst];
    float4 v = *(const float4*)(g_xw + src * HD + c * 4);
    float* op = o + dst * HD + c * 4;
    atomicAdd(op + 0, v.x * coef); atomicAdd(op + 1, v.y * coef);
    atomicAdd(op + 2, v.z * coef); atomicAdd(op + 3, v.w * coef);
}
__global__ void k_edge1(const int* __restrict__ ei, int E) { edge_body(g_xc1, ei, E); }
__global__ void k_edge2(const int* __restrict__ ei, int E) { edge_body(g_xc2, ei, E); }
__global__ void k_build_x(const int* __restrict__ idc, int N) {
    int gid = blockIdx.x * blockDim.x + threadIdx.x;
    if (gid >= N * 2 * HD) return;
    int n = gid / (2 * HD), j = gid - n * 2 * HD;
    float v = (j < HD) ? g_xc1[n * HD + j] : g_hn[idc[n] * HD + (j - HD)];
    g_x[gid] = fmaxf(v, 0.f);
}
__global__ void k_final(const int* __restrict__ idc, float* __restrict__ out, int N) {
    int gid = blockIdx.x * blockDim.x + threadIdx.x;
    if (gid >= N * 2 * HD) return;
    int n = gid / (2 * HD), j = gid - n * 2 * HD;
    out[gid] = (j < HD) ? fmaxf(g_xc2[n * HD + j], 0.f) : g_xc1[idc[n] * HD + (j - HD)];
}

extern "C" void kernel_launch(void* const* d_in, const int* in_sizes, int n_in,
                              void* d_out, int out_size)
{
    const int*   feat    = (const int*)  d_in[0];
    const int*   ei      = (const int*)  d_in[1];
    const int*   indices = (const int*)  d_in[2];
    const float* h0      = (const float*)d_in[3];
    const float* emb     = (const float*)d_in[4];
    const float* W_ih    = (const float*)d_in[5];
    const float* W_hh    = (const float*)d_in[6];
    const float* b_ih    = (const float*)d_in[7];
    const float* b_hh    = (const float*)d_in[8];
    const float* W1      = (const float*)d_in[9];
    const float* b1      = (const float*)d_in[10];
    const float* W2      = (const float*)d_in[11];
    const float* b2      = (const float*)d_in[12];
    float* out = (float*)d_out;

    const int N = in_sizes[0] / SEQL;
    const int E = in_sizes[1] / 2;
    const int V = in_sizes[4] / HD;
    const int gtiles = (N + NT - 1) / NT;
    const int etiles = (V + 63) / 64;

    cudaFuncSetAttribute(k_gru_mma, cudaFuncAttributeMaxDynamicSharedMemorySize, MMASMEM);
    cudaFuncSetAttribute(k_embW,    cudaFuncAttributeMaxDynamicSharedMemorySize, EMBW_SMEM);
    cudaFuncSetAttribute(k_gemm1,   cudaFuncAttributeMaxDynamicSharedMemorySize, (100*64 + 100*100) * 4);
    cudaFuncSetAttribute(k_gemm2,   cudaFuncAttributeMaxDynamicSharedMemorySize, (200*64 + 200*100) * 4);

    k_deg_init <<<(N + 255) / 256, 256>>>(N);
    k_deg_edges<<<(E + 255) / 256, 256>>>(ei, E);
    k_embW<<<NSM, 320, EMBW_SMEM>>>(emb, W_ih, b_ih, V, etiles);
    k_gru_mma<<<NSM, 640, MMASMEM>>>(h0, feat, W_hh, b_hh, N, gtiles);   // ncu slot 3
    k_dinv<<<(N + 255) / 256, 256>>>(N);

    k_gemm1<<<(N + 63) / 64, 256, (100*64 + 100*100) * 4>>>(W1, N);
    k_init1<<<(N * HD + 255) / 256, 256>>>(b1, N);
    k_edge1<<<(E * 25 + 255) / 256, 256>>>(ei, E);
    k_build_x<<<(N * 2 * HD + 255) / 256, 256>>>(indices, N);
    k_gemm2<<<(N + 63) / 64, 256, (200*64 + 200*100) * 4>>>(W2, N);
    k_init2<<<(N * HD + 255) / 256, 256>>>(b2, N);
    k_edge2<<<(E * 25 + 255) / 256, 256>>>(ei, E);
    k_final<<<(N * 2 * HD + 255) / 256, 256>>>(indices, out, N);
}

// round 13
// speedup vs baseline: 1.1566x; 1.0634x over previous
#include <cuda_runtime.h>
#include <cuda_bf16.h>
#include <cstdint>

#define NMAX   60000
#define VMAX   50000
#define SEQL   30
#define HD     100
#define G3     300
#define NSM    152

typedef unsigned long long u64;

__device__ float g_embW[VMAX * G3];
__device__ float g_hn  [NMAX * HD];
__device__ float g_xw  [NMAX * HD];
__device__ float g_xc1 [NMAX * HD];
__device__ float g_xc2 [NMAX * HD];
__device__ float g_x   [NMAX * 2*HD];
__device__ float g_dinv[NMAX];
__device__ int   g_deg [NMAX];

__device__ __forceinline__ u64 pack2(float lo, float hi) {
    u64 r; asm("mov.b64 %0, {%1, %2};" : "=l"(r) : "f"(lo), "f"(hi)); return r;
}
__device__ __forceinline__ void unpack2(u64 v, float &lo, float &hi) {
    asm("mov.b64 {%0, %1}, %2;" : "=f"(lo), "=f"(hi) : "l"(v));
}
__device__ __forceinline__ u64 fma2(u64 a, u64 b, u64 c) {
    u64 d; asm("fma.rn.f32x2 %0, %1, %2, %3;" : "=l"(d) : "l"(a), "l"(b), "l"(c)); return d;
}
__device__ __forceinline__ float sigmf(float x) { return __fdividef(1.f, 1.f + __expf(-x)); }
__device__ __forceinline__ float tanh_f(float x) {
    return fmaf(2.f, __fdividef(1.f, 1.f + __expf(-2.f * x)), -1.f);
}
__device__ __forceinline__ float bf16f(uint32_t b16) {
    uint32_t u = b16 << 16; float f; asm("mov.b32 %0, %1;" : "=f"(f) : "r"(u)); return f;
}
__device__ __forceinline__ uint32_t s2u(const void* p) {
    uint32_t a; asm("{ .reg .u64 t; cvta.to.shared.u64 t, %1; cvt.u32.u64 %0, t; }" : "=r"(a) : "l"(p));
    return a;
}

// ================= degree =================
__global__ void k_deg_init(int N) {
    int i = blockIdx.x * blockDim.x + threadIdx.x; if (i < N) g_deg[i] = 1;
}
__global__ void k_deg_edges(const int* __restrict__ ei, int E) {
    int e = blockIdx.x * blockDim.x + threadIdx.x; if (e < E) atomicAdd(&g_deg[ei[E + e]], 1);
}
__global__ void k_dinv(int N) {
    int i = blockIdx.x * blockDim.x + threadIdx.x; if (i < N) g_dinv[i] = rsqrtf((float)g_deg[i]);
}

// ================= embW table (fp32, proven) =================
#define EMBW_SMEM ((30000 + 6400) * 4)
__global__ __launch_bounds__(320, 1)
void k_embW(const float* __restrict__ emb, const float* __restrict__ W_ih,
            const float* __restrict__ b_ih, int V, int ntiles)
{
    extern __shared__ float sm[];
    float* sW = sm; float* se = sm + 30000;
    const int tid = threadIdx.x, n = tid & 63, jc = tid >> 6;
    for (int idx = tid; idx < G3 * HD; idx += 320) {
        int c = idx / HD, k = idx - c * HD;
        sW[k * G3 + c] = W_ih[idx];
    }
    for (int tile = blockIdx.x; tile < ntiles; tile += gridDim.x) {
        const int base = tile * 64;
        __syncthreads();
        for (int idx = tid; idx < 64 * HD; idx += 320) {
            int nn = idx / HD, k = idx - nn * HD;
            se[k * 64 + nn] = emb[min(base + nn, V - 1) * HD + k];
        }
        __syncthreads();
        u64 acc[30];
        #pragma unroll
        for (int p = 0; p < 30; p++) acc[p] = 0ull;
        const float* wr0 = sW + jc * 60;
        #pragma unroll 2
        for (int k = 0; k < HD; k++) {
            float xv = se[k * 64 + n];
            u64 x2 = pack2(xv, xv);
            const float* wr = wr0 + k * G3;
            #pragma unroll
            for (int p = 0; p < 30; p++) acc[p] = fma2(*(const u64*)(wr + p * 2), x2, acc[p]);
        }
        int v = base + n;
        if (v < V) {
            float* o = g_embW + (long long)v * G3 + jc * 60;
            const float* bp = b_ih + jc * 60;
            #pragma unroll
            for (int p = 0; p < 30; p++) {
                float lo, hi; unpack2(acc[p], lo, hi);
                float2 w; w.x = lo + bp[p*2]; w.y = hi + bp[p*2+1];
                *(float2*)(o + p*2) = w;
            }
        }
    }
}

// ================= HMMA GRU (mma.sync m16n8k16 bf16, 672 thr) =================
// 96-node tile = 6 m-tiles. 21 warps = 3 m-groups (2 m-tiles each) x 7
// q-slices (2 q-cols each; slice 6 has 1). Each B fragment load serves TWO
// mmas (both m-tiles) -> 1.67 wavefronts/mma, C stays at 48 regs/warp.
#define FRAG_OFF 0
#define A_OFF    139776
#define A_STR    496
#define NT       96
#define TOK_OFF  187392
#define BHH_OFF  198912
#define MMASMEM  200192

__global__ __launch_bounds__(672, 1)
void k_gru_mma(const float* __restrict__ h0, const int* __restrict__ feat,
               const float* __restrict__ W_hh, const float* __restrict__ b_hh,
               int n_nodes, int ntiles)
{
    extern __shared__ char smc[];
    const uint32_t sb = s2u(smc);
    const int tid = threadIdx.x, wid = tid >> 5, lane = tid & 31;
    const int qs = wid % 7, mg = wid / 7;           // qs 0..6, mg 0..2
    const int g = lane >> 2, t = lane & 3;
    const int qlo  = qs * 2;
    const int qcnt = (qs == 6) ? 1 : 2;             // q-cols 0..12 (13 total)
    float* sbhh = (float*)(smc + BHH_OFF);
    int*   stok = (int*)(smc + TOK_OFF);

    // ---- one-time: B fragments + biases ----
    for (int w = tid; w < 14 * 39 * 32; w += 672) {
        int lan = w & 31, tile = w >> 5;
        int nt = tile % 39, ktd = tile / 39;
        int gg = lan >> 2, tt = lan & 3;
        int gate = nt / 13, j = (nt % 13) * 8 + gg;
        bool isLo = (ktd >= 7);
        int k0 = (isLo ? ktd - 7 : ktd) * 16 + tt * 2;
        uint32_t br[2];
        #pragma unroll
        for (int r = 0; r < 2; r++) {
            uint32_t pk = 0;
            #pragma unroll
            for (int e = 0; e < 2; e++) {
                int kk = k0 + r * 8 + e;
                uint16_t bits = 0;
                if (j < 100 && kk < 100) {
                    float wv = W_hh[(gate * 100 + j) * 100 + kk];
                    __nv_bfloat16 hb = __float2bfloat16_rn(wv);
                    if (isLo) hb = __float2bfloat16_rn(wv - __bfloat162float(hb));
                    bits = __bfloat16_as_ushort(hb);
                }
                pk |= (uint32_t)bits << (16 * e);
            }
            br[r] = pk;
        }
        *(uint2*)(smc + FRAG_OFF + tile * 256 + lan * 8) = make_uint2(br[0], br[1]);
    }
    for (int i = tid; i < G3; i += 672) sbhh[i] = b_hh[i];
    __syncthreads();

    const int m0row = mg * 32;     // this warp's 32 rows (2 m-tiles)

    for (int tile = blockIdx.x; tile < ntiles; tile += gridDim.x) {
        const int nbase = tile * NT;
        __syncthreads();
        for (int i = tid; i < NT * SEQL; i += 672) {
            int nl = i / SEQL, tt = i - nl * SEQL;
            stok[nl * SEQL + tt] = feat[(long long)min(nbase + nl, n_nodes - 1) * SEQL + tt];
        }
        for (int i = tid; i < NT * 248; i += 672) {
            int row = i / 248, col = i - row * 248;
            uint16_t v = 0;
            if (col < 224) {
                int seg = col / 112, k = col - seg * 112;
                if (k < 100) {
                    float hv = h0[(long long)min(nbase + row, n_nodes - 1) * HD + k];
                    __nv_bfloat16 hb = __float2bfloat16_rn(hv);
                    if (seg == 1) hb = __float2bfloat16_rn(hv - __bfloat162float(hb));
                    v = __bfloat16_as_ushort(hb);
                }
            }
            *(uint16_t*)(smc + A_OFF + row * A_STR + col * 2) = v;
        }
        __syncthreads();

        for (int st = 0; st < SEQL; st++) {
            // ---- GEMM: gh = [h_hi|h_lo|h_hi] x [W_hi|W_hi|W_lo] ----
            float C[3][2][2][4];     // [gate][qi][mt][frag]
            #pragma unroll
            for (int ga = 0; ga < 3; ga++)
                #pragma unroll
                for (int qi = 0; qi < 2; qi++)
                    #pragma unroll
                    for (int mt = 0; mt < 2; mt++)
                        #pragma unroll
                        for (int e = 0; e < 4; e++) C[ga][qi][mt][e] = 0.f;

            const uint32_t ab0 = sb + A_OFF + (m0row + (lane & 15)) * A_STR + (lane >> 4) * 16;
            const uint32_t ab1 = ab0 + 16 * A_STR;
            #pragma unroll
            for (int kt = 0; kt < 21; kt++) {
                int acol = (kt < 7) ? kt * 32 : (kt < 14) ? 224 + (kt - 7) * 32 : (kt - 14) * 32;
                int ktd  = (kt < 7) ? kt : kt - 7;
                uint32_t a0, a1, a2, a3, c0, c1, c2, c3;
                asm volatile("ldmatrix.sync.aligned.m8n8.x4.shared.b16 {%0,%1,%2,%3}, [%4];"
                    : "=r"(a0), "=r"(a1), "=r"(a2), "=r"(a3) : "r"(ab0 + acol));
                asm volatile("ldmatrix.sync.aligned.m8n8.x4.shared.b16 {%0,%1,%2,%3}, [%4];"
                    : "=r"(c0), "=r"(c1), "=r"(c2), "=r"(c3) : "r"(ab1 + acol));
                #pragma unroll
                for (int ga = 0; ga < 3; ga++) {
                    #pragma unroll
                    for (int qi = 0; qi < 2; qi++) {
                        if (qi < qcnt) {
                            int nt = ga * 13 + qlo + qi;
                            uint32_t b0, b1;
                            asm volatile("ld.shared.v2.b32 {%0,%1}, [%2];"
                                : "=r"(b0), "=r"(b1)
                                : "r"(sb + FRAG_OFF + (ktd * 39 + nt) * 256 + lane * 8));
                            asm volatile(
                                "mma.sync.aligned.m16n8k16.row.col.f32.bf16.bf16.f32 "
                                "{%0,%1,%2,%3}, {%4,%5,%6,%7}, {%8,%9}, {%0,%1,%2,%3};"
                                : "+f"(C[ga][qi][0][0]), "+f"(C[ga][qi][0][1]),
                                  "+f"(C[ga][qi][0][2]), "+f"(C[ga][qi][0][3])
                                : "r"(a0), "r"(a1), "r"(a2), "r"(a3), "r"(b0), "r"(b1));
                            asm volatile(
                                "mma.sync.aligned.m16n8k16.row.col.f32.bf16.bf16.f32 "
                                "{%0,%1,%2,%3}, {%4,%5,%6,%7}, {%8,%9}, {%0,%1,%2,%3};"
                                : "+f"(C[ga][qi][1][0]), "+f"(C[ga][qi][1][1]),
                                  "+f"(C[ga][qi][1][2]), "+f"(C[ga][qi][1][3])
                                : "r"(c0), "r"(c1), "r"(c2), "r"(c3), "r"(b0), "r"(b1));
                        }
                    }
                }
            }
            __syncthreads();   // all A reads done before h writes

            // ---- gate phase ----
            const bool last = (st == SEQL - 1);
            #pragma unroll
            for (int qi = 0; qi < 2; qi++) {
                if (qi < qcnt) {
                    int j = (qlo + qi) * 8 + 2 * t;
                    if (j < 100) {
                        float2 bhr = *(const float2*)(sbhh + j);
                        float2 bhz = *(const float2*)(sbhh + 100 + j);
                        float2 bhn = *(const float2*)(sbhh + 200 + j);
                        #pragma unroll
                        for (int mt = 0; mt < 2; mt++) {
                            #pragma unroll
                            for (int nd = 0; nd < 2; nd++) {
                                int nl = m0row + mt * 16 + nd * 8 + g;
                                int gn = nbase + nl;
                                int tok = stok[nl * SEQL + st];
                                const float* ew = g_embW + (long long)tok * G3;
                                float2 xr = __ldg((const float2*)(ew + j));
                                float2 xz = __ldg((const float2*)(ew + 100 + j));
                                float2 xn = __ldg((const float2*)(ew + 200 + j));
                                char* hrow = smc + A_OFF + nl * A_STR;
                                uint32_t hhi = *(uint32_t*)(hrow + 2 * j);
                                uint32_t hlo = *(uint32_t*)(hrow + 224 + 2 * j);
                                float ho0 = bf16f(hhi & 0xffffu) + bf16f(hlo & 0xffffu);
                                float ho1 = bf16f(hhi >> 16) + bf16f(hlo >> 16);
                                float r0 = sigmf(xr.x + C[0][qi][mt][2*nd]   + bhr.x);
                                float r1 = sigmf(xr.y + C[0][qi][mt][2*nd+1] + bhr.y);
                                float z0 = sigmf(xz.x + C[1][qi][mt][2*nd]   + bhz.x);
                                float z1 = sigmf(xz.y + C[1][qi][mt][2*nd+1] + bhz.y);
                                float nv0 = tanh_f(xn.x + r0 * (C[2][qi][mt][2*nd]   + bhn.x));
                                float nv1 = tanh_f(xn.y + r1 * (C[2][qi][mt][2*nd+1] + bhn.y));
                                float h0n = nv0 + z0 * (ho0 - nv0);
                                float h1n = nv1 + z1 * (ho1 - nv1);
                                if (last) {
                                    if (gn < n_nodes)
                                        *(float2*)(g_hn + (long long)gn * HD + j) = make_float2(h0n, h1n);
                                } else {
                                    __nv_bfloat16 ah = __float2bfloat16_rn(h0n);
                                    __nv_bfloat16 bh = __float2bfloat16_rn(h1n);
                                    __nv_bfloat16 al = __float2bfloat16_rn(h0n - __bfloat162float(ah));
                                    __nv_bfloat16 bl = __float2bfloat16_rn(h1n - __bfloat162float(bh));
                                    *(uint32_t*)(hrow + 2 * j) =
                                        (uint32_t)__bfloat16_as_ushort(ah) |
                                        ((uint32_t)__bfloat16_as_ushort(bh) << 16);
                                    *(uint32_t*)(hrow + 224 + 2 * j) =
                                        (uint32_t)__bfloat16_as_ushort(al) |
                                        ((uint32_t)__bfloat16_as_ushort(bl) << 16);
                                }
                            }
                        }
                    }
                }
            }
            __syncthreads();   // h writes visible before next step's GEMM
        }
    }
}

// ================= small GEMMs / GCN / glue (proven) =================
template<int K>
__device__ __forceinline__ void gemm_body(const float* __restrict__ x,
    const float* __restrict__ W, float* __restrict__ outp, int N)
{
    extern __shared__ float sg[];
    float* sxT = sg; float* sW = sg + K * 64;
    const int tid = threadIdx.x, base = blockIdx.x * 64;
    for (int idx = tid; idx < K * 64; idx += 256) {
        int nn = idx / K, k = idx - nn * K;
        sxT[k * 64 + nn] = x[min(base + nn, N - 1) * K + k];
    }
    for (int idx = tid; idx < K * 100; idx += 256) sW[idx] = W[idx];
    __syncthreads();
    const int n = tid & 63, q = tid >> 6;
    float acc[25];
    #pragma unroll
    for (int j = 0; j < 25; j++) acc[j] = 0.f;
    #pragma unroll 4
    for (int k = 0; k < K; k++) {
        float xk = sxT[k * 64 + n];
        const float* wr = sW + k * 100 + q * 25;
        #pragma unroll
        for (int j = 0; j < 25; j++) acc[j] = fmaf(xk, wr[j], acc[j]);
    }
    int ng = base + n;
    if (ng < N) {
        float* o = outp + ng * 100 + q * 25;
        #pragma unroll
        for (int j = 0; j < 25; j++) o[j] = acc[j];
    }
}
__global__ __launch_bounds__(256) void k_gemm1(const float* __restrict__ W1, int N) {
    gemm_body<100>(g_hn, W1, g_xw, N);
}
__global__ __launch_bounds__(256) void k_gemm2(const float* __restrict__ W2, int N) {
    gemm_body<200>(g_x, W2, g_xw, N);
}
__device__ __forceinline__ void init_self(const float* __restrict__ b, float* __restrict__ o, int N) {
    int gid = blockIdx.x * blockDim.x + threadIdx.x;
    if (gid >= N * HD) return;
    int n = gid / HD, j = gid - n * HD;
    float di = g_dinv[n];
    o[gid] = fmaf(g_xw[gid], di * di, b[j]);
}
__global__ void k_init1(const float* __restrict__ b1, int N) { init_self(b1, g_xc1, N); }
__global__ void k_init2(const float* __restrict__ b2, int N) { init_self(b2, g_xc2, N); }
__device__ __forceinline__ void edge_body(float* __restrict__ o, const int* __restrict__ ei, int E) {
    int gid = blockIdx.x * blockDim.x + threadIdx.x;
    if (gid >= E * 25) return;
    int e = gid / 25, c = gid - e * 25;
    int src = ei[e], dst = ei[E + e];
    float coef = g_dinv[src] * g_dinv[dst];
    float4 v = *(const float4*)(g_xw + src * HD + c * 4);
    float* op = o + dst * HD + c * 4;
    atomicAdd(op + 0, v.x * coef); atomicAdd(op + 1, v.y * coef);
    atomicAdd(op + 2, v.z * coef); atomicAdd(op + 3, v.w * coef);
}
__global__ void k_edge1(const int* __restrict__ ei, int E) { edge_body(g_xc1, ei, E); }
__global__ void k_edge2(const int* __restrict__ ei, int E) { edge_body(g_xc2, ei, E); }
__global__ void k_build_x(const int* __restrict__ idc, int N) {
    int gid = blockIdx.x * blockDim.x + threadIdx.x;
    if (gid >= N * 2 * HD) return;
    int n = gid / (2 * HD), j = gid - n * 2 * HD;
    float v = (j < HD) ? g_xc1[n * HD + j] : g_hn[idc[n] * HD + (j - HD)];
    g_x[gid] = fmaxf(v, 0.f);
}
__global__ void k_final(const int* __restrict__ idc, float* __restrict__ out, int N) {
    int gid = blockIdx.x * blockDim.x + threadIdx.x;
    if (gid >= N * 2 * HD) return;
    int n = gid / (2 * HD), j = gid - n * 2 * HD;
    out[gid] = (j < HD) ? fmaxf(g_xc2[n * HD + j], 0.f) : g_xc1[idc[n] * HD + (j - HD)];
}

extern "C" void kernel_launch(void* const* d_in, const int* in_sizes, int n_in,
                              void* d_out, int out_size)
{
    const int*   feat    = (const int*)  d_in[0];
    const int*   ei      = (const int*)  d_in[1];
    const int*   indices = (const int*)  d_in[2];
    const float* h0      = (const float*)d_in[3];
    const float* emb     = (const float*)d_in[4];
    const float* W_ih    = (const float*)d_in[5];
    const float* W_hh    = (const float*)d_in[6];
    const float* b_ih    = (const float*)d_in[7];
    const float* b_hh    = (const float*)d_in[8];
    const float* W1      = (const float*)d_in[9];
    const float* b1      = (const float*)d_in[10];
    const float* W2      = (const float*)d_in[11];
    const float* b2      = (const float*)d_in[12];
    float* out = (float*)d_out;

    const int N = in_sizes[0] / SEQL;
    const int E = in_sizes[1] / 2;
    const int V = in_sizes[4] / HD;
    const int gtiles = (N + NT - 1) / NT;
    const int etiles = (V + 63) / 64;

    cudaFuncSetAttribute(k_gru_mma, cudaFuncAttributeMaxDynamicSharedMemorySize, MMASMEM);
    cudaFuncSetAttribute(k_embW,    cudaFuncAttributeMaxDynamicSharedMemorySize, EMBW_SMEM);
    cudaFuncSetAttribute(k_gemm1,   cudaFuncAttributeMaxDynamicSharedMemorySize, (100*64 + 100*100) * 4);
    cudaFuncSetAttribute(k_gemm2,   cudaFuncAttributeMaxDynamicSharedMemorySize, (200*64 + 200*100) * 4);

    k_deg_init <<<(N + 255) / 256, 256>>>(N);
    k_deg_edges<<<(E + 255) / 256, 256>>>(ei, E);
    k_embW<<<NSM, 320, EMBW_SMEM>>>(emb, W_ih, b_ih, V, etiles);
    k_gru_mma<<<NSM, 672, MMASMEM>>>(h0, feat, W_hh, b_hh, N, gtiles);   // ncu slot 3
    k_dinv<<<(N + 255) / 256, 256>>>(N);

    k_gemm1<<<(N + 63) / 64, 256, (100*64 + 100*100) * 4>>>(W1, N);
    k_init1<<<(N * HD + 255) / 256, 256>>>(b1, N);
    k_edge1<<<(E * 25 + 255) / 256, 256>>>(ei, E);
    k_build_x<<<(N * 2 * HD + 255) / 256, 256>>>(indices, N);
    k_gemm2<<<(N + 63) / 64, 256, (200*64 + 200*100) * 4>>>(W2, N);
    k_init2<<<(N * HD + 255) / 256, 256>>>(b2, N);
    k_edge2<<<(E * 25 + 255) / 256, 256>>>(ei, E);
    k_final<<<(N * 2 * HD + 255) / 256, 256>>>(indices, out, N);
}

// round 14
// speedup vs baseline: 1.2889x; 1.1144x over previous
#include <cuda_runtime.h>
#include <cuda_bf16.h>
#include <cstdint>

#define NMAX   60000
#define VMAX   50000
#define SEQL   30
#define HD     100
#define G3     300
#define NSM    152

typedef unsigned long long u64;

__device__ float g_embW[VMAX * G3];
__device__ float g_hn  [NMAX * HD];
__device__ float g_xw  [NMAX * HD];
__device__ float g_xc1 [NMAX * HD];
__device__ float g_xc2 [NMAX * HD];
__device__ float g_x   [NMAX * 2*HD];
__device__ float g_dinv[NMAX];
__device__ int   g_deg [NMAX];

__device__ __forceinline__ u64 pack2(float lo, float hi) {
    u64 r; asm("mov.b64 %0, {%1, %2};" : "=l"(r) : "f"(lo), "f"(hi)); return r;
}
__device__ __forceinline__ void unpack2(u64 v, float &lo, float &hi) {
    asm("mov.b64 {%0, %1}, %2;" : "=f"(lo), "=f"(hi) : "l"(v));
}
__device__ __forceinline__ u64 fma2(u64 a, u64 b, u64 c) {
    u64 d; asm("fma.rn.f32x2 %0, %1, %2, %3;" : "=l"(d) : "l"(a), "l"(b), "l"(c)); return d;
}
__device__ __forceinline__ float sigmf(float x) { return __fdividef(1.f, 1.f + __expf(-x)); }
__device__ __forceinline__ float tanh_f(float x) {
    return fmaf(2.f, __fdividef(1.f, 1.f + __expf(-2.f * x)), -1.f);
}
__device__ __forceinline__ float bf16f(uint32_t b16) {
    uint32_t u = b16 << 16; float f; asm("mov.b32 %0, %1;" : "=f"(f) : "r"(u)); return f;
}
__device__ __forceinline__ uint32_t s2u(const void* p) {
    uint32_t a; asm("{ .reg .u64 t; cvta.to.shared.u64 t, %1; cvt.u32.u64 %0, t; }" : "=r"(a) : "l"(p));
    return a;
}

// ================= degree =================
__global__ void k_deg_init(int N) {
    int i = blockIdx.x * blockDim.x + threadIdx.x; if (i < N) g_deg[i] = 1;
}
__global__ void k_deg_edges(const int* __restrict__ ei, int E) {
    int e = blockIdx.x * blockDim.x + threadIdx.x; if (e < E) atomicAdd(&g_deg[ei[E + e]], 1);
}
__global__ void k_dinv(int N) {
    int i = blockIdx.x * blockDim.x + threadIdx.x; if (i < N) g_dinv[i] = rsqrtf((float)g_deg[i]);
}

// ================= embW table (fp32, proven) =================
#define EMBW_SMEM ((30000 + 6400) * 4)
__global__ __launch_bounds__(320, 1)
void k_embW(const float* __restrict__ emb, const float* __restrict__ W_ih,
            const float* __restrict__ b_ih, int V, int ntiles)
{
    extern __shared__ float sm[];
    float* sW = sm; float* se = sm + 30000;
    const int tid = threadIdx.x, n = tid & 63, jc = tid >> 6;
    for (int idx = tid; idx < G3 * HD; idx += 320) {
        int c = idx / HD, k = idx - c * HD;
        sW[k * G3 + c] = W_ih[idx];
    }
    for (int tile = blockIdx.x; tile < ntiles; tile += gridDim.x) {
        const int base = tile * 64;
        __syncthreads();
        for (int idx = tid; idx < 64 * HD; idx += 320) {
            int nn = idx / HD, k = idx - nn * HD;
            se[k * 64 + nn] = emb[min(base + nn, V - 1) * HD + k];
        }
        __syncthreads();
        u64 acc[30];
        #pragma unroll
        for (int p = 0; p < 30; p++) acc[p] = 0ull;
        const float* wr0 = sW + jc * 60;
        #pragma unroll 2
        for (int k = 0; k < HD; k++) {
            float xv = se[k * 64 + n];
            u64 x2 = pack2(xv, xv);
            const float* wr = wr0 + k * G3;
            #pragma unroll
            for (int p = 0; p < 30; p++) acc[p] = fma2(*(const u64*)(wr + p * 2), x2, acc[p]);
        }
        int v = base + n;
        if (v < V) {
            float* o = g_embW + (long long)v * G3 + jc * 60;
            const float* bp = b_ih + jc * 60;
            #pragma unroll
            for (int p = 0; p < 30; p++) {
                float lo, hi; unpack2(acc[p], lo, hi);
                float2 w; w.x = lo + bp[p*2]; w.y = hi + bp[p*2+1];
                *(float2*)(o + p*2) = w;
            }
        }
    }
}

// ================= HMMA GRU (mma.sync m16n8k16 bf16, 672 thr) =================
// 96-node tile = 6 m-tiles. 21 warps = 3 m-groups (2 m-tiles each) x 7
// q-slices. Each m-group (7 warps, 224 thr) owns h rows [mg*32, mg*32+32)
// exclusively in the step loop -> per-group NAMED barriers (bar.sync mg+1,224)
// instead of CTA-wide __syncthreads: groups free-run, gate phase of one group
// overlaps GEMM of another.
#define FRAG_OFF 0
#define A_OFF    139776
#define A_STR    496
#define NT       96
#define TOK_OFF  187392
#define BHH_OFF  198912
#define MMASMEM  200192

__global__ __launch_bounds__(672, 1)
void k_gru_mma(const float* __restrict__ h0, const int* __restrict__ feat,
               const float* __restrict__ W_hh, const float* __restrict__ b_hh,
               int n_nodes, int ntiles)
{
    extern __shared__ char smc[];
    const uint32_t sb = s2u(smc);
    const int tid = threadIdx.x, wid = tid >> 5, lane = tid & 31;
    const int qs = wid % 7, mg = wid / 7;           // qs 0..6, mg 0..2
    const int g = lane >> 2, t = lane & 3;
    const int qlo  = qs * 2;
    const int qcnt = (qs == 6) ? 1 : 2;             // q-cols 0..12 (13 total)
    const int barid = mg + 1;                       // named barrier per m-group
    float* sbhh = (float*)(smc + BHH_OFF);
    int*   stok = (int*)(smc + TOK_OFF);

    // ---- one-time: B fragments + biases ----
    for (int w = tid; w < 14 * 39 * 32; w += 672) {
        int lan = w & 31, tile = w >> 5;
        int nt = tile % 39, ktd = tile / 39;
        int gg = lan >> 2, tt = lan & 3;
        int gate = nt / 13, j = (nt % 13) * 8 + gg;
        bool isLo = (ktd >= 7);
        int k0 = (isLo ? ktd - 7 : ktd) * 16 + tt * 2;
        uint32_t br[2];
        #pragma unroll
        for (int r = 0; r < 2; r++) {
            uint32_t pk = 0;
            #pragma unroll
            for (int e = 0; e < 2; e++) {
                int kk = k0 + r * 8 + e;
                uint16_t bits = 0;
                if (j < 100 && kk < 100) {
                    float wv = W_hh[(gate * 100 + j) * 100 + kk];
                    __nv_bfloat16 hb = __float2bfloat16_rn(wv);
                    if (isLo) hb = __float2bfloat16_rn(wv - __bfloat162float(hb));
                    bits = __bfloat16_as_ushort(hb);
                }
                pk |= (uint32_t)bits << (16 * e);
            }
            br[r] = pk;
        }
        *(uint2*)(smc + FRAG_OFF + tile * 256 + lan * 8) = make_uint2(br[0], br[1]);
    }
    for (int i = tid; i < G3; i += 672) sbhh[i] = b_hh[i];
    __syncthreads();

    const int m0row = mg * 32;     // this warp's 32 rows (2 m-tiles)

    for (int tile = blockIdx.x; tile < ntiles; tile += gridDim.x) {
        const int nbase = tile * NT;
        __syncthreads();   // all groups done with previous tile's h/stok
        for (int i = tid; i < NT * SEQL; i += 672) {
            int nl = i / SEQL, tt = i - nl * SEQL;
            stok[nl * SEQL + tt] = feat[(long long)min(nbase + nl, n_nodes - 1) * SEQL + tt];
        }
        for (int i = tid; i < NT * 248; i += 672) {
            int row = i / 248, col = i - row * 248;
            uint16_t v = 0;
            if (col < 224) {
                int seg = col / 112, k = col - seg * 112;
                if (k < 100) {
                    float hv = h0[(long long)min(nbase + row, n_nodes - 1) * HD + k];
                    __nv_bfloat16 hb = __float2bfloat16_rn(hv);
                    if (seg == 1) hb = __float2bfloat16_rn(hv - __bfloat162float(hb));
                    v = __bfloat16_as_ushort(hb);
                }
            }
            *(uint16_t*)(smc + A_OFF + row * A_STR + col * 2) = v;
        }
        __syncthreads();

        for (int st = 0; st < SEQL; st++) {
            // ---- GEMM: gh = [h_hi|h_lo|h_hi] x [W_hi|W_hi|W_lo] ----
            float C[3][2][2][4];     // [gate][qi][mt][frag]
            #pragma unroll
            for (int ga = 0; ga < 3; ga++)
                #pragma unroll
                for (int qi = 0; qi < 2; qi++)
                    #pragma unroll
                    for (int mt = 0; mt < 2; mt++)
                        #pragma unroll
                        for (int e = 0; e < 4; e++) C[ga][qi][mt][e] = 0.f;

            const uint32_t ab0 = sb + A_OFF + (m0row + (lane & 15)) * A_STR + (lane >> 4) * 16;
            const uint32_t ab1 = ab0 + 16 * A_STR;
            #pragma unroll
            for (int kt = 0; kt < 21; kt++) {
                int acol = (kt < 7) ? kt * 32 : (kt < 14) ? 224 + (kt - 7) * 32 : (kt - 14) * 32;
                int ktd  = (kt < 7) ? kt : kt - 7;
                uint32_t a0, a1, a2, a3, c0, c1, c2, c3;
                asm volatile("ldmatrix.sync.aligned.m8n8.x4.shared.b16 {%0,%1,%2,%3}, [%4];"
                    : "=r"(a0), "=r"(a1), "=r"(a2), "=r"(a3) : "r"(ab0 + acol));
                asm volatile("ldmatrix.sync.aligned.m8n8.x4.shared.b16 {%0,%1,%2,%3}, [%4];"
                    : "=r"(c0), "=r"(c1), "=r"(c2), "=r"(c3) : "r"(ab1 + acol));
                #pragma unroll
                for (int ga = 0; ga < 3; ga++) {
                    #pragma unroll
                    for (int qi = 0; qi < 2; qi++) {
                        if (qi < qcnt) {
                            int nt = ga * 13 + qlo + qi;
                            uint32_t b0, b1;
                            asm volatile("ld.shared.v2.b32 {%0,%1}, [%2];"
                                : "=r"(b0), "=r"(b1)
                                : "r"(sb + FRAG_OFF + (ktd * 39 + nt) * 256 + lane * 8));
                            asm volatile(
                                "mma.sync.aligned.m16n8k16.row.col.f32.bf16.bf16.f32 "
                                "{%0,%1,%2,%3}, {%4,%5,%6,%7}, {%8,%9}, {%0,%1,%2,%3};"
                                : "+f"(C[ga][qi][0][0]), "+f"(C[ga][qi][0][1]),
                                  "+f"(C[ga][qi][0][2]), "+f"(C[ga][qi][0][3])
                                : "r"(a0), "r"(a1), "r"(a2), "r"(a3), "r"(b0), "r"(b1));
                            asm volatile(
                                "mma.sync.aligned.m16n8k16.row.col.f32.bf16.bf16.f32 "
                                "{%0,%1,%2,%3}, {%4,%5,%6,%7}, {%8,%9}, {%0,%1,%2,%3};"
                                : "+f"(C[ga][qi][1][0]), "+f"(C[ga][qi][1][1]),
                                  "+f"(C[ga][qi][1][2]), "+f"(C[ga][qi][1][3])
                                : "r"(c0), "r"(c1), "r"(c2), "r"(c3), "r"(b0), "r"(b1));
                        }
                    }
                }
            }
            // group-local barrier: this group's A reads done before its h writes
            asm volatile("bar.sync %0, 224;" :: "r"(barid) : "memory");

            // ---- gate phase ----
            const bool last = (st == SEQL - 1);
            #pragma unroll
            for (int qi = 0; qi < 2; qi++) {
                if (qi < qcnt) {
                    int j = (qlo + qi) * 8 + 2 * t;
                    if (j < 100) {
                        float2 bhr = *(const float2*)(sbhh + j);
                        float2 bhz = *(const float2*)(sbhh + 100 + j);
                        float2 bhn = *(const float2*)(sbhh + 200 + j);
                        #pragma unroll
                        for (int mt = 0; mt < 2; mt++) {
                            #pragma unroll
                            for (int nd = 0; nd < 2; nd++) {
                                int nl = m0row + mt * 16 + nd * 8 + g;
                                int gn = nbase + nl;
                                int tok = stok[nl * SEQL + st];
                                const float* ew = g_embW + (long long)tok * G3;
                                float2 xr = __ldg((const float2*)(ew + j));
                                float2 xz = __ldg((const float2*)(ew + 100 + j));
                                float2 xn = __ldg((const float2*)(ew + 200 + j));
                                char* hrow = smc + A_OFF + nl * A_STR;
                                uint32_t hhi = *(uint32_t*)(hrow + 2 * j);
                                uint32_t hlo = *(uint32_t*)(hrow + 224 + 2 * j);
                                float ho0 = bf16f(hhi & 0xffffu) + bf16f(hlo & 0xffffu);
                                float ho1 = bf16f(hhi >> 16) + bf16f(hlo >> 16);
                                float r0 = sigmf(xr.x + C[0][qi][mt][2*nd]   + bhr.x);
                                float r1 = sigmf(xr.y + C[0][qi][mt][2*nd+1] + bhr.y);
                                float z0 = sigmf(xz.x + C[1][qi][mt][2*nd]   + bhz.x);
                                float z1 = sigmf(xz.y + C[1][qi][mt][2*nd+1] + bhz.y);
                                float nv0 = tanh_f(xn.x + r0 * (C[2][qi][mt][2*nd]   + bhn.x));
                                float nv1 = tanh_f(xn.y + r1 * (C[2][qi][mt][2*nd+1] + bhn.y));
                                float h0n = nv0 + z0 * (ho0 - nv0);
                                float h1n = nv1 + z1 * (ho1 - nv1);
                                if (last) {
                                    if (gn < n_nodes)
                                        *(float2*)(g_hn + (long long)gn * HD + j) = make_float2(h0n, h1n);
                                } else {
                                    __nv_bfloat16 ah = __float2bfloat16_rn(h0n);
                                    __nv_bfloat16 bh = __float2bfloat16_rn(h1n);
                                    __nv_bfloat16 al = __float2bfloat16_rn(h0n - __bfloat162float(ah));
                                    __nv_bfloat16 bl = __float2bfloat16_rn(h1n - __bfloat162float(bh));
                                    *(uint32_t*)(hrow + 2 * j) =
                                        (uint32_t)__bfloat16_as_ushort(ah) |
                                        ((uint32_t)__bfloat16_as_ushort(bh) << 16);
                                    *(uint32_t*)(hrow + 224 + 2 * j) =
                                        (uint32_t)__bfloat16_as_ushort(al) |
                                        ((uint32_t)__bfloat16_as_ushort(bl) << 16);
                                }
                            }
                        }
                    }
                }
            }
            // group-local barrier: h writes visible before next step's GEMM
            asm volatile("bar.sync %0, 224;" :: "r"(barid) : "memory");
        }
    }
}

// ================= small GEMMs / GCN / glue (proven) =================
template<int K>
__device__ __forceinline__ void gemm_body(const float* __restrict__ x,
    const float* __restrict__ W, float* __restrict__ outp, int N)
{
    extern __shared__ float sg[];
    float* sxT = sg; float* sW = sg + K * 64;
    const int tid = threadIdx.x, base = blockIdx.x * 64;
    for (int idx = tid; idx < K * 64; idx += 256) {
        int nn = idx / K, k = idx - nn * K;
        sxT[k * 64 + nn] = x[min(base + nn, N - 1) * K + k];
    }
    for (int idx = tid; idx < K * 100; idx += 256) sW[idx] = W[idx];
    __syncthreads();
    const int n = tid & 63, q = tid >> 6;
    float acc[25];
    #pragma unroll
    for (int j = 0; j < 25; j++) acc[j] = 0.f;
    #pragma unroll 4
    for (int k = 0; k < K; k++) {
        float xk = sxT[k * 64 + n];
        const float* wr = sW + k * 100 + q * 25;
        #pragma unroll
        for (int j = 0; j < 25; j++) acc[j] = fmaf(xk, wr[j], acc[j]);
    }
    int ng = base + n;
    if (ng < N) {
        float* o = outp + ng * 100 + q * 25;
        #pragma unroll
        for (int j = 0; j < 25; j++) o[j] = acc[j];
    }
}
__global__ __launch_bounds__(256) void k_gemm1(const float* __restrict__ W1, int N) {
    gemm_body<100>(g_hn, W1, g_xw, N);
}
__global__ __launch_bounds__(256) void k_gemm2(const float* __restrict__ W2, int N) {
    gemm_body<200>(g_x, W2, g_xw, N);
}
__device__ __forceinline__ void init_self(const float* __restrict__ b, float* __restrict__ o, int N) {
    int gid = blockIdx.x * blockDim.x + threadIdx.x;
    if (gid >= N * HD) return;
    int n = gid / HD, j = gid - n * HD;
    float di = g_dinv[n];
    o[gid] = fmaf(g_xw[gid], di * di, b[j]);
}
__global__ void k_init1(const float* __restrict__ b1, int N) { init_self(b1, g_xc1, N); }
__global__ void k_init2(const float* __restrict__ b2, int N) { init_self(b2, g_xc2, N); }
__device__ __forceinline__ void edge_body(float* __restrict__ o, const int* __restrict__ ei, int E) {
    int gid = blockIdx.x * blockDim.x + threadIdx.x;
    if (gid >= E * 25) return;
    int e = gid / 25, c = gid - e * 25;
    int src = ei[e], dst = ei[E + e];
    float coef = g_dinv[src] * g_dinv[dst];
    float4 v = *(const float4*)(g_xw + src * HD + c * 4);
    float* op = o + dst * HD + c * 4;
    atomicAdd(op + 0, v.x * coef); atomicAdd(op + 1, v.y * coef);
    atomicAdd(op + 2, v.z * coef); atomicAdd(op + 3, v.w * coef);
}
__global__ void k_edge1(const int* __restrict__ ei, int E) { edge_body(g_xc1, ei, E); }
__global__ void k_edge2(const int* __restrict__ ei, int E) { edge_body(g_xc2, ei, E); }
__global__ void k_build_x(const int* __restrict__ idc, int N) {
    int gid = blockIdx.x * blockDim.x + threadIdx.x;
    if (gid >= N * 2 * HD) return;
    int n = gid / (2 * HD), j = gid - n * 2 * HD;
    float v = (j < HD) ? g_xc1[n * HD + j] : g_hn[idc[n] * HD + (j - HD)];
    g_x[gid] = fmaxf(v, 0.f);
}
__global__ void k_final(const int* __restrict__ idc, float* __restrict__ out, int N) {
    int gid = blockIdx.x * blockDim.x + threadIdx.x;
    if (gid >= N * 2 * HD) return;
    int n = gid / (2 * HD), j = gid - n * 2 * HD;
    out[gid] = (j < HD) ? fmaxf(g_xc2[n * HD + j], 0.f) : g_xc1[idc[n] * HD + (j - HD)];
}

extern "C" void kernel_launch(void* const* d_in, const int* in_sizes, int n_in,
                              void* d_out, int out_size)
{
    const int*   feat    = (const int*)  d_in[0];
    const int*   ei      = (const int*)  d_in[1];
    const int*   indices = (const int*)  d_in[2];
    const float* h0      = (const float*)d_in[3];
    const float* emb     = (const float*)d_in[4];
    const float* W_ih    = (const float*)d_in[5];
    const float* W_hh    = (const float*)d_in[6];
    const float* b_ih    = (const float*)d_in[7];
    const float* b_hh    = (const float*)d_in[8];
    const float* W1      = (const float*)d_in[9];
    const float* b1      = (const float*)d_in[10];
    const float* W2      = (const float*)d_in[11];
    const float* b2      = (const float*)d_in[12];
    float* out = (float*)d_out;

    const int N = in_sizes[0] / SEQL;
    const int E = in_sizes[1] / 2;
    const int V = in_sizes[4] / HD;
    const int gtiles = (N + NT - 1) / NT;
    const int etiles = (V + 63) / 64;

    cudaFuncSetAttribute(k_gru_mma, cudaFuncAttributeMaxDynamicSharedMemorySize, MMASMEM);
    cudaFuncSetAttribute(k_embW,    cudaFuncAttributeMaxDynamicSharedMemorySize, EMBW_SMEM);
    cudaFuncSetAttribute(k_gemm1,   cudaFuncAttributeMaxDynamicSharedMemorySize, (100*64 + 100*100) * 4);
    cudaFuncSetAttribute(k_gemm2,   cudaFuncAttributeMaxDynamicSharedMemorySize, (200*64 + 200*100) * 4);

    k_deg_init <<<(N + 255) / 256, 256>>>(N);
    k_deg_edges<<<(E + 255) / 256, 256>>>(ei, E);
    k_embW<<<NSM, 320, EMBW_SMEM>>>(emb, W_ih, b_ih, V, etiles);
    k_gru_mma<<<NSM, 672, MMASMEM>>>(h0, feat, W_hh, b_hh, N, gtiles);   // ncu slot 3
    k_dinv<<<(N + 255) / 256, 256>>>(N);

    k_gemm1<<<(N + 63) / 64, 256, (100*64 + 100*100) * 4>>>(W1, N);
    k_init1<<<(N * HD + 255) / 256, 256>>>(b1, N);
    k_edge1<<<(E * 25 + 255) / 256, 256>>>(ei, E);
    k_build_x<<<(N * 2 * HD + 255) / 256, 256>>>(indices, N);
    k_gemm2<<<(N + 63) / 64, 256, (200*64 + 200*100) * 4>>>(W2, N);
    k_init2<<<(N * HD + 255) / 256, 256>>>(b2, N);
    k_edge2<<<(E * 25 + 255) / 256, 256>>>(ei, E);
    k_final<<<(N * 2 * HD + 255) / 256, 256>>>(indices, out, N);
}